// round 1
// baseline (speedup 1.0000x reference)
#include <cuda_runtime.h>
#include <cuda_bf16.h>
#include <stdint.h>

#define NODES   100000
#define MAX_E   3200000
#define SCAN_BS 1024
#define NB      ((NODES + SCAN_BS - 1) / SCAN_BS)   // 98
#define TILE    128
#define K4_THREADS 256
#define FSTRIDE 72    // s_feats row stride in floats (2-way-minimal bank pattern for LDS/STS.64)
#define CSTRIDE 20    // s_cf / s_emb row stride (conflict-free for frag loads)

// ---------------- scratch (static device globals; no runtime allocation) ----------------
__device__ int   g_counts[NODES];
__device__ int   g_cursor[NODES];
__device__ float g_den[NODES];
__device__ int   g_bsum[NB];
__device__ int   g_snode[MAX_E];
__device__ int   g_seid[MAX_E];
__device__ float g_sw[MAX_E];

// ---------------- small helpers ----------------
__device__ __forceinline__ unsigned f2tf32(float f) {
    unsigned r;
    asm("cvt.rna.tf32.f32 %0, %1;" : "=r"(r) : "f"(f));
    return r;
}

__device__ __forceinline__ void mma_tf32(float& d0, float& d1, float& d2, float& d3,
                                         unsigned a0, unsigned a1, unsigned a2, unsigned a3,
                                         unsigned b0, unsigned b1) {
    asm volatile(
        "mma.sync.aligned.m16n8k8.row.col.f32.tf32.tf32.f32 "
        "{%0,%1,%2,%3}, {%4,%5,%6,%7}, {%8,%9}, {%0,%1,%2,%3};"
        : "+f"(d0), "+f"(d1), "+f"(d2), "+f"(d3)
        : "r"(a0), "r"(a1), "r"(a2), "r"(a3), "r"(b0), "r"(b1));
}

// ---------------- K0: zero per-node scratch ----------------
__global__ void k_zero() {
    int i = blockIdx.x * blockDim.x + threadIdx.x;
    if (i < NODES) { g_counts[i] = 0; g_den[i] = 0.0f; }
}

// ---------------- K1: per-node edge counts + weight sums ----------------
__global__ void k_count(const int* __restrict__ idx, const float* __restrict__ w, int E) {
    int e = blockIdx.x * blockDim.x + threadIdx.x;
    if (e >= E) return;
    int n = idx[e];
    atomicAdd(&g_counts[n], 1);
    atomicAdd(&g_den[n], w[e]);
}

// ---------------- K2: exclusive scan counts -> cursor (3 kernels) ----------------
__global__ void k_scan1() {
    __shared__ int wsum[32];
    int t = threadIdx.x, b = blockIdx.x;
    int i = b * SCAN_BS + t;
    int lane = t & 31, wp = t >> 5;
    int v = (i < NODES) ? g_counts[i] : 0;
    int x = v;
#pragma unroll
    for (int d = 1; d < 32; d <<= 1) {
        int y = __shfl_up_sync(0xffffffffu, x, d);
        if (lane >= d) x += y;
    }
    if (lane == 31) wsum[wp] = x;
    __syncthreads();
    if (wp == 0) {
        int s = wsum[lane];
#pragma unroll
        for (int d = 1; d < 32; d <<= 1) {
            int y = __shfl_up_sync(0xffffffffu, s, d);
            if (lane >= d) s += y;
        }
        wsum[lane] = s;
    }
    __syncthreads();
    int base = wp ? wsum[wp - 1] : 0;
    if (i < NODES) g_cursor[i] = base + x - v;   // block-local exclusive
    if (t == 0) g_bsum[b] = wsum[31];            // block total
}

__global__ void k_scan2() {   // 1 block, 128 threads: exclusive scan of g_bsum[NB]
    __shared__ int sh[4];
    int t = threadIdx.x, lane = t & 31, wp = t >> 5;
    int v = (t < NB) ? g_bsum[t] : 0;
    int x = v;
#pragma unroll
    for (int d = 1; d < 32; d <<= 1) {
        int y = __shfl_up_sync(0xffffffffu, x, d);
        if (lane >= d) x += y;
    }
    if (lane == 31) sh[wp] = x;
    __syncthreads();
    if (t == 0) {
        int a = 0;
#pragma unroll
        for (int k = 0; k < 4; k++) { int tmp = sh[k]; sh[k] = a; a += tmp; }
    }
    __syncthreads();
    if (t < NB) g_bsum[t] = sh[wp] + x - v;
}

__global__ void k_scan3() {
    int i = blockIdx.x * SCAN_BS + threadIdx.x;
    if (i < NODES) g_cursor[i] += g_bsum[blockIdx.x];
}

// ---------------- K3: scatter edges into node-sorted order; fold 1/den into w ----------------
__global__ void k_scatter(const int* __restrict__ idx, const float* __restrict__ w, int E) {
    int e = blockIdx.x * blockDim.x + threadIdx.x;
    if (e >= E) return;
    int n = idx[e];
    int p = atomicAdd(&g_cursor[n], 1);
    g_seid[p]  = e;
    g_snode[p] = n;
    g_sw[p]    = w[e] / g_den[n];   // premultiplied: segment-sum of w'*relu(feat) IS the output
}

// ---------------- K4: fused tf32 MMA + segmented reduction over sorted tiles ----------------
__global__ void __launch_bounds__(K4_THREADS)
k_main(const float* __restrict__ emb, const float* __restrict__ cf,
       float* __restrict__ out, int E) {
    __shared__ __align__(16) float    s_feats[TILE * FSTRIDE];   // 36864 B (rows: edges, cols: u)
    __shared__ __align__(16) unsigned s_emb[64 * CSTRIDE];       // 5120 B (tf32 bits)
    __shared__ int   s_node[TILE];
    __shared__ float s_w[TILE];
    unsigned* s_cf = (unsigned*)s_feats;                         // aliased: [TILE][CSTRIDE] tf32

    int t = threadIdx.x;
    int b = blockIdx.x;
    int base = b * TILE;

    // --- load embedding (64x16) -> smem as tf32 ---
    for (int j = t; j < 64 * 16; j += K4_THREADS) {
        int u = j >> 4, f = j & 15;
        s_emb[u * CSTRIDE + f] = f2tf32(emb[j]);
    }

    // --- gather cf tile (128 edges x 16 feats) -> s_cf as tf32 ---
    {
        int i = t >> 1, h = t & 1;           // edge-in-tile, half (8 floats each)
        int g = base + i;
        float4 p0 = make_float4(0.f, 0.f, 0.f, 0.f), p1 = p0;
        if (g < E) {
            int eid = g_seid[g];
            const float4* cp = (const float4*)(cf + (size_t)eid * 16);
            p0 = cp[h * 2];
            p1 = cp[h * 2 + 1];
        }
        unsigned r0 = f2tf32(p0.x), r1 = f2tf32(p0.y), r2 = f2tf32(p0.z), r3 = f2tf32(p0.w);
        unsigned r4 = f2tf32(p1.x), r5 = f2tf32(p1.y), r6 = f2tf32(p1.z), r7 = f2tf32(p1.w);
        unsigned* dst = s_cf + i * CSTRIDE + h * 8;   // 16B aligned (80B row stride, 32B half)
        *(uint4*)(dst)     = make_uint4(r0, r1, r2, r3);
        *(uint4*)(dst + 4) = make_uint4(r4, r5, r6, r7);
    }
    if (t < TILE) {
        int g = base + t;
        if (g < E) { s_node[t] = g_snode[g]; s_w[t] = g_sw[g]; }
        else       { s_node[t] = 0;          s_w[t] = 0.0f;    }
    }
    __syncthreads();

    // --- per-warp A fragments (rows = 16 edges per warp), w factors ---
    int wp = t >> 5, l = t & 31;
    int row = wp * 16 + (l >> 2);
    int c   = l & 3;
    unsigned a0 = s_cf[row * CSTRIDE + c];
    unsigned a1 = s_cf[(row + 8) * CSTRIDE + c];
    unsigned a2 = s_cf[row * CSTRIDE + c + 4];
    unsigned a3 = s_cf[(row + 8) * CSTRIDE + c + 4];
    unsigned a4 = s_cf[row * CSTRIDE + c + 8];
    unsigned a5 = s_cf[(row + 8) * CSTRIDE + c + 8];
    unsigned a6 = s_cf[row * CSTRIDE + c + 12];
    unsigned a7 = s_cf[(row + 8) * CSTRIDE + c + 12];
    float w_lo = s_w[row], w_hi = s_w[row + 8];
    __syncthreads();   // A frags in regs before s_feats overwrites the aliased s_cf

    // --- 16 MMAs per warp: 16 edges x 64 u, K=16 in 2 steps; relu * w' -> s_feats ---
#pragma unroll
    for (int nt = 0; nt < 8; nt++) {
        int er = nt * 8 + (l >> 2);
        unsigned b0 = s_emb[er * CSTRIDE + c];
        unsigned b1 = s_emb[er * CSTRIDE + c + 4];
        unsigned b2 = s_emb[er * CSTRIDE + c + 8];
        unsigned b3 = s_emb[er * CSTRIDE + c + 12];
        float d0 = 0.f, d1 = 0.f, d2 = 0.f, d3 = 0.f;
        mma_tf32(d0, d1, d2, d3, a0, a1, a2, a3, b0, b1);
        mma_tf32(d0, d1, d2, d3, a4, a5, a6, a7, b2, b3);
        d0 = fmaxf(d0, 0.f) * w_lo;
        d1 = fmaxf(d1, 0.f) * w_lo;
        d2 = fmaxf(d2, 0.f) * w_hi;
        d3 = fmaxf(d3, 0.f) * w_hi;
        int col = nt * 8 + 2 * c;
        *(float2*)&s_feats[row * FSTRIDE + col]       = make_float2(d0, d1);
        *(float2*)&s_feats[(row + 8) * FSTRIDE + col] = make_float2(d2, d3);
    }
    __syncthreads();

    // --- segmented reduction: warp 0, lane = u-pair; sorted => s_node non-decreasing ---
    if (wp == 0) {
        int vr  = min(TILE, E - base);
        int cur = s_node[0];
        float2 acc = make_float2(0.f, 0.f);
        bool first = true;   // first span may continue a node from the previous tile -> atomic
        for (int r = 0; r < vr; r++) {
            int nd = s_node[r];
            if (nd != cur) {
                float* dst = out + (size_t)cur * 64 + 2 * l;
                if (first) { atomicAdd(dst, acc.x); atomicAdd(dst + 1, acc.y); }
                else       { *(float2*)dst = acc; }          // node interior to this tile
                first = false;
                acc = make_float2(0.f, 0.f);
                cur = nd;
            }
            float2 v = *(float2*)&s_feats[r * FSTRIDE + 2 * l];
            acc.x += v.x;
            acc.y += v.y;
        }
        float* dst = out + (size_t)cur * 64 + 2 * l;         // last span may continue -> atomic
        atomicAdd(dst, acc.x);
        atomicAdd(dst + 1, acc.y);
    }
}

// ---------------- launch ----------------
extern "C" void kernel_launch(void* const* d_in, const int* in_sizes, int n_in,
                              void* d_out, int out_size) {
    const float* emb = (const float*)d_in[0];   // [64,16]
    const float* cf  = (const float*)d_in[1];   // [E,16]
    const float* w   = (const float*)d_in[2];   // [E]
    const int*   idx = (const int*)d_in[3];     // [E]
    int E = in_sizes[2];
    float* out = (float*)d_out;                 // [100000,64]

    cudaMemsetAsync(d_out, 0, (size_t)out_size * sizeof(float));
    k_zero<<<(NODES + 255) / 256, 256>>>();

    int eb = (E + 255) / 256;
    k_count<<<eb, 256>>>(idx, w, E);
    k_scan1<<<NB, SCAN_BS>>>();
    k_scan2<<<1, 128>>>();
    k_scan3<<<NB, SCAN_BS>>>();
    k_scatter<<<eb, 256>>>(idx, w, E);

    int nt = (E + TILE - 1) / TILE;
    k_main<<<nt, K4_THREADS>>>(emb, cf, out, E);
}

// round 2
// speedup vs baseline: 1.3174x; 1.3174x over previous
#include <cuda_runtime.h>
#include <stdint.h>

#define NODES   100000
#define MAX_E   3200000
#define SCAN_BS 1024
#define NB      ((NODES + SCAN_BS - 1) / SCAN_BS)   // 98
#define TILE    128
#define K4_THREADS 256
#define FSTRIDE 72    // s_feats row stride (floats)
#define CSTRIDE 20    // s_cf / s_emb row stride (tf32 words)
#define DEN_FX  16777216.0f   // 2^24 fixed-point scale for den

// ---------------- scratch (static device globals) ----------------
__device__ unsigned long long g_cd[NODES];   // hi32 = count, lo32 = den in 2^-24 fixed point
__device__ int   g_cursor[NODES];
__device__ int   g_bsum[NB];
__device__ uint4 g_pack[MAX_E];              // {eid, node, bits(w/den), 0}

// ---------------- helpers ----------------
__device__ __forceinline__ unsigned f2tf32(float f) {
    unsigned r;
    asm("cvt.rna.tf32.f32 %0, %1;" : "=r"(r) : "f"(f));
    return r;
}

__device__ __forceinline__ void mma_tf32(float& d0, float& d1, float& d2, float& d3,
                                         unsigned a0, unsigned a1, unsigned a2, unsigned a3,
                                         unsigned b0, unsigned b1) {
    asm volatile(
        "mma.sync.aligned.m16n8k8.row.col.f32.tf32.tf32.f32 "
        "{%0,%1,%2,%3}, {%4,%5,%6,%7}, {%8,%9}, {%0,%1,%2,%3};"
        : "+f"(d0), "+f"(d1), "+f"(d2), "+f"(d3)
        : "r"(a0), "r"(a1), "r"(a2), "r"(a3), "r"(b0), "r"(b1));
}

// ---------------- K0: zero out + per-node scratch ----------------
__global__ void k_zero(float4* __restrict__ out4, int n4) {
    int i = blockIdx.x * blockDim.x + threadIdx.x;
    if (i < n4) out4[i] = make_float4(0.f, 0.f, 0.f, 0.f);
    if (i < NODES) g_cd[i] = 0ULL;
}

// ---------------- K1: fused count + weight-sum (one 64-bit atomic per edge) ----------------
__global__ void k_count(const int* __restrict__ idx, const float* __restrict__ w, int E) {
    int e = blockIdx.x * blockDim.x + threadIdx.x;
    if (e >= E) return;
    int n = idx[e];
    unsigned fx = __float2uint_rn(w[e] * DEN_FX);
    atomicAdd(&g_cd[n], (1ULL << 32) | (unsigned long long)fx);
}

// ---------------- K2a: block-local exclusive scan of counts ----------------
__global__ void k_scan1() {
    __shared__ int wsum[32];
    int t = threadIdx.x, b = blockIdx.x;
    int i = b * SCAN_BS + t;
    int lane = t & 31, wp = t >> 5;
    int v = (i < NODES) ? (int)(g_cd[i] >> 32) : 0;
    int x = v;
#pragma unroll
    for (int d = 1; d < 32; d <<= 1) {
        int y = __shfl_up_sync(0xffffffffu, x, d);
        if (lane >= d) x += y;
    }
    if (lane == 31) wsum[wp] = x;
    __syncthreads();
    if (wp == 0) {
        int s = wsum[lane];
#pragma unroll
        for (int d = 1; d < 32; d <<= 1) {
            int y = __shfl_up_sync(0xffffffffu, s, d);
            if (lane >= d) s += y;
        }
        wsum[lane] = s;
    }
    __syncthreads();
    int base = wp ? wsum[wp - 1] : 0;
    if (i < NODES) g_cursor[i] = base + x - v;
    if (t == 0) g_bsum[b] = wsum[31];
}

// ---------------- K2b: fused global offset (each block re-sums bsum prefix) ----------------
__global__ void k_scan23() {
    __shared__ int s_off;
    int t = threadIdx.x, b = blockIdx.x;
    if (t < 32) {
        int s = 0;
        for (int j = t; j < b; j += 32) s += g_bsum[j];
#pragma unroll
        for (int d = 16; d >= 1; d >>= 1) s += __shfl_xor_sync(0xffffffffu, s, d);
        if (t == 0) s_off = s;
    }
    __syncthreads();
    int i = b * SCAN_BS + t;
    if (i < NODES) g_cursor[i] += s_off;
}

// ---------------- K3: scatter packed payload (single STG.128 per edge) ----------------
__global__ void k_scatter(const int* __restrict__ idx, const float* __restrict__ w, int E) {
    int e = blockIdx.x * blockDim.x + threadIdx.x;
    if (e >= E) return;
    int n = idx[e];
    int p = atomicAdd(&g_cursor[n], 1);
    float den = (float)(unsigned)(g_cd[n] & 0xffffffffULL) * (1.0f / DEN_FX);
    float wp = w[e] / den;
    g_pack[p] = make_uint4((unsigned)e, (unsigned)n, __float_as_uint(wp), 0u);
}

// ---------------- K4: fused tf32 MMA + 4-warp segmented reduction ----------------
__global__ void __launch_bounds__(K4_THREADS)
k_main(const float* __restrict__ emb, const float* __restrict__ cf,
       float* __restrict__ out, int E) {
    __shared__ __align__(16) float    s_feats[TILE * FSTRIDE];   // 36864 B
    __shared__ __align__(16) unsigned s_emb[64 * CSTRIDE];       // 5120 B
    __shared__ int      s_node[TILE];
    __shared__ float    s_w[TILE];
    __shared__ unsigned s_eid[TILE];
    __shared__ float    s_pbuf[8][64];                            // chunk boundary partials
    __shared__ int      s_pn[8];
    __shared__ int      s_ev[8];
    unsigned* s_cf = (unsigned*)s_feats;                          // aliased [TILE][CSTRIDE]

    int t = threadIdx.x;
    int base = blockIdx.x * TILE;
    int wp = t >> 5, l = t & 31;

    // --- packed side-load (t<128): one LDG.128 per edge ---
    unsigned my_eid = 0u;
    int g = base + t;
    if (t < TILE) {
        uint4 pk = make_uint4(0u, 0u, 0u, 0u);
        if (g < E) pk = g_pack[g];
        my_eid    = pk.x;
        s_eid[t]  = pk.x;
        s_node[t] = (int)pk.y;
        s_w[t]    = __uint_as_float(pk.z);
    }
    if (t < 8) s_ev[t] = 0;

    // --- embedding (64x16) -> smem tf32 ---
    for (int j = t; j < 64 * 16; j += K4_THREADS) {
        int u = j >> 4, f = j & 15;
        s_emb[u * CSTRIDE + f] = f2tf32(emb[j]);
    }

    // --- gather cf: t<128 loads bytes [0,32) of edge t (eid already in reg) ---
    float4 p0 = make_float4(0.f, 0.f, 0.f, 0.f), p1 = p0;
    if (t < TILE && g < E) {
        const float4* cp = (const float4*)(cf + (size_t)my_eid * 16);
        p0 = cp[0]; p1 = cp[1];
    }
    __syncthreads();   // s_eid visible to upper half
    int i = (t < TILE) ? t : (t - TILE);
    int h = (t < TILE) ? 0 : 1;
    if (t >= TILE) {
        int g2 = base + i;
        if (g2 < E) {
            const float4* cp = (const float4*)(cf + (size_t)s_eid[i] * 16);
            p0 = cp[2]; p1 = cp[3];
        }
    }
    {
        unsigned r0 = f2tf32(p0.x), r1 = f2tf32(p0.y), r2 = f2tf32(p0.z), r3 = f2tf32(p0.w);
        unsigned r4 = f2tf32(p1.x), r5 = f2tf32(p1.y), r6 = f2tf32(p1.z), r7 = f2tf32(p1.w);
        unsigned* dst = s_cf + i * CSTRIDE + h * 8;
        *(uint4*)(dst)     = make_uint4(r0, r1, r2, r3);
        *(uint4*)(dst + 4) = make_uint4(r4, r5, r6, r7);
    }
    __syncthreads();

    // --- per-warp A fragments (16 edge-rows per warp) ---
    int row = wp * 16 + (l >> 2);
    int c   = l & 3;
    unsigned a0 = s_cf[row * CSTRIDE + c];
    unsigned a1 = s_cf[(row + 8) * CSTRIDE + c];
    unsigned a2 = s_cf[row * CSTRIDE + c + 4];
    unsigned a3 = s_cf[(row + 8) * CSTRIDE + c + 4];
    unsigned a4 = s_cf[row * CSTRIDE + c + 8];
    unsigned a5 = s_cf[(row + 8) * CSTRIDE + c + 8];
    unsigned a6 = s_cf[row * CSTRIDE + c + 12];
    unsigned a7 = s_cf[(row + 8) * CSTRIDE + c + 12];
    float w_lo = s_w[row], w_hi = s_w[row + 8];
    __syncthreads();   // A frags in regs before s_feats overwrites aliased s_cf

    // --- 16 MMAs/warp: 16 edges x 64 u; relu * w' -> s_feats ---
#pragma unroll
    for (int nt = 0; nt < 8; nt++) {
        int er = nt * 8 + (l >> 2);
        unsigned b0 = s_emb[er * CSTRIDE + c];
        unsigned b1 = s_emb[er * CSTRIDE + c + 4];
        unsigned b2 = s_emb[er * CSTRIDE + c + 8];
        unsigned b3 = s_emb[er * CSTRIDE + c + 12];
        float d0 = 0.f, d1 = 0.f, d2 = 0.f, d3 = 0.f;
        mma_tf32(d0, d1, d2, d3, a0, a1, a2, a3, b0, b1);
        mma_tf32(d0, d1, d2, d3, a4, a5, a6, a7, b2, b3);
        d0 = fmaxf(d0, 0.f) * w_lo;
        d1 = fmaxf(d1, 0.f) * w_lo;
        d2 = fmaxf(d2, 0.f) * w_hi;
        d3 = fmaxf(d3, 0.f) * w_hi;
        int col = nt * 8 + 2 * c;
        *(float2*)&s_feats[row * FSTRIDE + col]       = make_float2(d0, d1);
        *(float2*)&s_feats[(row + 8) * FSTRIDE + col] = make_float2(d2, d3);
    }
    __syncthreads();

    // --- phase 1: warps 0-3 reduce 32-row chunks; interiors stored, boundaries stashed ---
    int vr = min(TILE, E - base);
    if (wp < 4) {
        int lo = wp * 32;
        if (lo < vr) {
            int hi = min(lo + 32, vr);
            int cur = s_node[lo];
            float2 acc = make_float2(0.f, 0.f);
            int nseg = 0;
            for (int r = lo; r < hi; r++) {
                int nd = s_node[r];
                if (nd != cur) {
                    if (nseg == 0) {
                        s_pbuf[2 * wp][2 * l]     = acc.x;
                        s_pbuf[2 * wp][2 * l + 1] = acc.y;
                        if (l == 0) { s_pn[2 * wp] = cur; s_ev[2 * wp] = 1; }
                    } else {
                        *(float2*)(out + (size_t)cur * 64 + 2 * l) = acc;  // complete segment
                    }
                    nseg++;
                    cur = nd;
                    acc = make_float2(0.f, 0.f);
                }
                float2 v = *(float2*)&s_feats[r * FSTRIDE + 2 * l];
                acc.x += v.x; acc.y += v.y;
            }
            s_pbuf[2 * wp + 1][2 * l]     = acc.x;
            s_pbuf[2 * wp + 1][2 * l + 1] = acc.y;
            if (l == 0) { s_pn[2 * wp + 1] = cur; s_ev[2 * wp + 1] = 1; }
        }
    }
    __syncthreads();

    // --- phase 2: warp 0 merges <=8 boundary partials in order ---
    if (wp == 0) {
        int cur = -1;
        float2 acc = make_float2(0.f, 0.f);
        bool first = true;
#pragma unroll
        for (int e2 = 0; e2 < 8; e2++) {
            if (!s_ev[e2]) continue;
            int nd = s_pn[e2];
            float2 v = *(float2*)&s_pbuf[e2][2 * l];
            if (nd != cur) {
                if (cur >= 0) {
                    float* dst = out + (size_t)cur * 64 + 2 * l;
                    if (first) { atomicAdd(dst, acc.x); atomicAdd(dst + 1, acc.y); first = false; }
                    else       { *(float2*)dst = acc; }   // complete interior span
                }
                cur = nd;
                acc = v;
            } else { acc.x += v.x; acc.y += v.y; }
        }
        float* dst = out + (size_t)cur * 64 + 2 * l;   // last span may continue into next block
        atomicAdd(dst, acc.x);
        atomicAdd(dst + 1, acc.y);
    }
}

// ---------------- launch ----------------
extern "C" void kernel_launch(void* const* d_in, const int* in_sizes, int n_in,
                              void* d_out, int out_size) {
    const float* emb = (const float*)d_in[0];   // [64,16]
    const float* cf  = (const float*)d_in[1];   // [E,16]
    const float* w   = (const float*)d_in[2];   // [E]
    const int*   idx = (const int*)d_in[3];     // [E]
    int E = in_sizes[2];
    float* out = (float*)d_out;                 // [100000,64]

    int n4 = out_size / 4;
    k_zero<<<(n4 + 255) / 256, 256>>>((float4*)d_out, n4);

    int eb = (E + 255) / 256;
    k_count<<<eb, 256>>>(idx, w, E);
    k_scan1<<<NB, SCAN_BS>>>();
    k_scan23<<<NB, SCAN_BS>>>();
    k_scatter<<<eb, 256>>>(idx, w, E);

    int nt = (E + TILE - 1) / TILE;
    k_main<<<nt, K4_THREADS>>>(emb, cf, out, E);
}

// round 3
// speedup vs baseline: 1.3495x; 1.0243x over previous
#include <cuda_runtime.h>
#include <stdint.h>

#define NODES   100000
#define MAX_E   3200000
#define SCAN_BS 1024
#define NB      ((NODES + SCAN_BS - 1) / SCAN_BS)   // 98
#define TILE    128
#define K4_THREADS 256
#define FSTRIDE 72    // s_feats row stride (floats)
#define CSTRIDE 20    // s_cf / s_emb row stride (tf32 words)
#define DEN_FX  16777216.0f   // 2^24 fixed-point scale for den

// ---------------- scratch (static device globals) ----------------
__device__ unsigned long long g_cd[NODES];   // hi32 = count, lo32 = den (2^-24 fixed)
__device__ int   g_cursor[NODES];
__device__ float g_invden[NODES];
__device__ int   g_bsum[NB];
__device__ uint4 g_pack[MAX_E];              // {eid, node, bits(w), 0}

// ---------------- helpers ----------------
__device__ __forceinline__ unsigned f2tf32(float f) {
    unsigned r;
    asm("cvt.rna.tf32.f32 %0, %1;" : "=r"(r) : "f"(f));
    return r;
}

__device__ __forceinline__ void mma_tf32(float& d0, float& d1, float& d2, float& d3,
                                         unsigned a0, unsigned a1, unsigned a2, unsigned a3,
                                         unsigned b0, unsigned b1) {
    asm volatile(
        "mma.sync.aligned.m16n8k8.row.col.f32.tf32.tf32.f32 "
        "{%0,%1,%2,%3}, {%4,%5,%6,%7}, {%8,%9}, {%0,%1,%2,%3};"
        : "+f"(d0), "+f"(d1), "+f"(d2), "+f"(d3)
        : "r"(a0), "r"(a1), "r"(a2), "r"(a3), "r"(b0), "r"(b1));
}

// ---------------- K1: fused count + weight-sum (one 64-bit RED per edge) ----------------
// g_cd is zero on entry: statically on call 1, re-zeroed by k_scan1 on later replays.
__global__ void k_count(const int* __restrict__ idx, const float* __restrict__ w, int E) {
    int e = blockIdx.x * blockDim.x + threadIdx.x;
    if (e >= E) return;
    int n = idx[e];
    unsigned fx = __float2uint_rn(w[e] * DEN_FX);
    atomicAdd(&g_cd[n], (1ULL << 32) | (unsigned long long)fx);
}

// ---------------- K2a: block-local exclusive scan; emits invden; re-zeroes g_cd ----------------
__global__ void k_scan1() {
    __shared__ int wsum[32];
    int t = threadIdx.x, b = blockIdx.x;
    int i = b * SCAN_BS + t;
    int lane = t & 31, wp = t >> 5;
    unsigned long long cd = (i < NODES) ? g_cd[i] : 0ULL;
    int v = (int)(cd >> 32);
    if (i < NODES) {
        g_cd[i] = 0ULL;                                   // clean for next replay
        g_invden[i] = __fdividef(DEN_FX, (float)(unsigned)(cd & 0xffffffffULL));
    }
    int x = v;
#pragma unroll
    for (int d = 1; d < 32; d <<= 1) {
        int y = __shfl_up_sync(0xffffffffu, x, d);
        if (lane >= d) x += y;
    }
    if (lane == 31) wsum[wp] = x;
    __syncthreads();
    if (wp == 0) {
        int s = wsum[lane];
#pragma unroll
        for (int d = 1; d < 32; d <<= 1) {
            int y = __shfl_up_sync(0xffffffffu, s, d);
            if (lane >= d) s += y;
        }
        wsum[lane] = s;
    }
    __syncthreads();
    int base = wp ? wsum[wp - 1] : 0;
    if (i < NODES) g_cursor[i] = base + x - v;
    if (t == 0) g_bsum[b] = wsum[31];
}

// ---------------- K2b: global offsets (each block re-sums its bsum prefix) ----------------
__global__ void k_scan23() {
    __shared__ int s_off;
    int t = threadIdx.x, b = blockIdx.x;
    if (t < 32) {
        int s = 0;
        for (int j = t; j < b; j += 32) s += g_bsum[j];
#pragma unroll
        for (int d = 16; d >= 1; d >>= 1) s += __shfl_xor_sync(0xffffffffu, s, d);
        if (t == 0) s_off = s;
    }
    __syncthreads();
    int i = b * SCAN_BS + t;
    if (i < NODES) g_cursor[i] += s_off;
}

// ---------------- K3: scatter packed payload + zero the output buffer ----------------
__global__ void k_scatter(const int* __restrict__ idx, const float* __restrict__ w,
                          float4* __restrict__ out4, int n4, int E) {
    int e = blockIdx.x * blockDim.x + threadIdx.x;
    // zero out[] (poisoned / previous replay's values); completes before k_main by stream order
    for (int z = e; z < n4; z += gridDim.x * blockDim.x)
        out4[z] = make_float4(0.f, 0.f, 0.f, 0.f);
    if (e >= E) return;
    int n = idx[e];
    int p = atomicAdd(&g_cursor[n], 1);
    g_pack[p] = make_uint4((unsigned)e, (unsigned)n, __float_as_uint(w[e]), 0u);
}

// ---------------- K4: fused tf32 MMA + 8-warp segmented reduction ----------------
__global__ void __launch_bounds__(K4_THREADS)
k_main(const float* __restrict__ emb, const float* __restrict__ cf,
       float* __restrict__ out, int E) {
    __shared__ __align__(16) float    s_feats[TILE * FSTRIDE];   // 36864 B
    __shared__ __align__(16) unsigned s_emb[64 * CSTRIDE];       // 5120 B
    __shared__ int      s_node[TILE];
    __shared__ float    s_w[TILE];
    __shared__ unsigned s_eid[TILE];
    __shared__ float    s_pbuf[16][64];                           // boundary partials
    __shared__ int      s_pn[16];
    __shared__ int      s_ev[16];
    unsigned* s_cf = (unsigned*)s_feats;                          // aliased [TILE][CSTRIDE]

    int t = threadIdx.x;
    int base = blockIdx.x * TILE;
    int wp = t >> 5, l = t & 31;

    // --- packed side-load (t<128): one LDG.128 per edge ---
    unsigned my_eid = 0u;
    int g = base + t;
    if (t < TILE) {
        uint4 pk = make_uint4(0u, 0u, 0u, 0u);
        if (g < E) pk = g_pack[g];
        my_eid    = pk.x;
        s_eid[t]  = pk.x;
        s_node[t] = (int)pk.y;
        s_w[t]    = __uint_as_float(pk.z);
    }
    if (t < 16) s_ev[t] = 0;

    // --- embedding (64x16) -> smem tf32 ---
    for (int j = t; j < 64 * 16; j += K4_THREADS) {
        int u = j >> 4, f = j & 15;
        s_emb[u * CSTRIDE + f] = f2tf32(emb[j]);
    }

    // --- gather cf: lower half loads bytes [0,32), upper half [32,64) of each edge ---
    float4 p0 = make_float4(0.f, 0.f, 0.f, 0.f), p1 = p0;
    if (t < TILE && g < E) {
        const float4* cp = (const float4*)(cf + (size_t)my_eid * 16);
        p0 = cp[0]; p1 = cp[1];
    }
    __syncthreads();   // s_eid visible to upper half
    int i = (t < TILE) ? t : (t - TILE);
    int h = (t < TILE) ? 0 : 1;
    if (t >= TILE) {
        int g2 = base + i;
        if (g2 < E) {
            const float4* cp = (const float4*)(cf + (size_t)s_eid[i] * 16);
            p0 = cp[2]; p1 = cp[3];
        }
    }
    {
        unsigned r0 = f2tf32(p0.x), r1 = f2tf32(p0.y), r2 = f2tf32(p0.z), r3 = f2tf32(p0.w);
        unsigned r4 = f2tf32(p1.x), r5 = f2tf32(p1.y), r6 = f2tf32(p1.z), r7 = f2tf32(p1.w);
        unsigned* dst = s_cf + i * CSTRIDE + h * 8;
        *(uint4*)(dst)     = make_uint4(r0, r1, r2, r3);
        *(uint4*)(dst + 4) = make_uint4(r4, r5, r6, r7);
    }
    __syncthreads();

    // --- per-warp A fragments (16 edge-rows per warp) ---
    int row = wp * 16 + (l >> 2);
    int c   = l & 3;
    unsigned a0 = s_cf[row * CSTRIDE + c];
    unsigned a1 = s_cf[(row + 8) * CSTRIDE + c];
    unsigned a2 = s_cf[row * CSTRIDE + c + 4];
    unsigned a3 = s_cf[(row + 8) * CSTRIDE + c + 4];
    unsigned a4 = s_cf[row * CSTRIDE + c + 8];
    unsigned a5 = s_cf[(row + 8) * CSTRIDE + c + 8];
    unsigned a6 = s_cf[row * CSTRIDE + c + 12];
    unsigned a7 = s_cf[(row + 8) * CSTRIDE + c + 12];
    float w_lo = s_w[row], w_hi = s_w[row + 8];
    __syncthreads();   // A frags in regs before s_feats overwrites aliased s_cf

    // --- 16 MMAs/warp: 16 edges x 64 u; relu * w -> s_feats ---
#pragma unroll
    for (int nt = 0; nt < 8; nt++) {
        int er = nt * 8 + (l >> 2);
        unsigned b0 = s_emb[er * CSTRIDE + c];
        unsigned b1 = s_emb[er * CSTRIDE + c + 4];
        unsigned b2 = s_emb[er * CSTRIDE + c + 8];
        unsigned b3 = s_emb[er * CSTRIDE + c + 12];
        float d0 = 0.f, d1 = 0.f, d2 = 0.f, d3 = 0.f;
        mma_tf32(d0, d1, d2, d3, a0, a1, a2, a3, b0, b1);
        mma_tf32(d0, d1, d2, d3, a4, a5, a6, a7, b2, b3);
        d0 = fmaxf(d0, 0.f) * w_lo;
        d1 = fmaxf(d1, 0.f) * w_lo;
        d2 = fmaxf(d2, 0.f) * w_hi;
        d3 = fmaxf(d3, 0.f) * w_hi;
        int col = nt * 8 + 2 * c;
        *(float2*)&s_feats[row * FSTRIDE + col]       = make_float2(d0, d1);
        *(float2*)&s_feats[(row + 8) * FSTRIDE + col] = make_float2(d2, d3);
    }
    __syncthreads();

    // --- phase 1: 8 warps x 16 rows; complete segments stored scaled, boundaries stashed ---
    int vr = min(TILE, E - base);
    {
        int lo = wp * 16;
        if (lo < vr) {
            int hi = min(lo + 16, vr);
            int cur = s_node[lo];
            float2 acc = make_float2(0.f, 0.f);
            int nseg = 0;
            for (int r = lo; r < hi; r++) {
                int nd = s_node[r];
                if (nd != cur) {
                    if (nseg == 0) {
                        s_pbuf[2 * wp][2 * l]     = acc.x;
                        s_pbuf[2 * wp][2 * l + 1] = acc.y;
                        if (l == 0) { s_pn[2 * wp] = cur; s_ev[2 * wp] = 1; }
                    } else {
                        float invd = g_invden[cur];        // complete segment: scale + store
                        *(float2*)(out + (size_t)cur * 64 + 2 * l) =
                            make_float2(acc.x * invd, acc.y * invd);
                    }
                    nseg++;
                    cur = nd;
                    acc = make_float2(0.f, 0.f);
                }
                float2 v = *(float2*)&s_feats[r * FSTRIDE + 2 * l];
                acc.x += v.x; acc.y += v.y;
            }
            s_pbuf[2 * wp + 1][2 * l]     = acc.x;
            s_pbuf[2 * wp + 1][2 * l + 1] = acc.y;
            if (l == 0) { s_pn[2 * wp + 1] = cur; s_ev[2 * wp + 1] = 1; }
        }
    }
    __syncthreads();

    // --- phase 2: warp 0 merges <=16 boundary partials in row order ---
    if (wp == 0) {
        int cur = -1;
        float2 acc = make_float2(0.f, 0.f);
        bool first = true;
#pragma unroll
        for (int e2 = 0; e2 < 16; e2++) {
            if (!s_ev[e2]) continue;
            int nd = s_pn[e2];
            float2 v = *(float2*)&s_pbuf[e2][2 * l];
            if (nd != cur) {
                if (cur >= 0) {
                    float invd = g_invden[cur];
                    float* dst = out + (size_t)cur * 64 + 2 * l;
                    if (first) {
                        atomicAdd(dst, acc.x * invd);
                        atomicAdd(dst + 1, acc.y * invd);
                        first = false;
                    } else {
                        *(float2*)dst = make_float2(acc.x * invd, acc.y * invd);
                    }
                }
                cur = nd;
                acc = v;
            } else { acc.x += v.x; acc.y += v.y; }
        }
        float invd = g_invden[cur];
        float* dst = out + (size_t)cur * 64 + 2 * l;   // may continue into next block
        atomicAdd(dst, acc.x * invd);
        atomicAdd(dst + 1, acc.y * invd);
    }
}

// ---------------- launch ----------------
extern "C" void kernel_launch(void* const* d_in, const int* in_sizes, int n_in,
                              void* d_out, int out_size) {
    const float* emb = (const float*)d_in[0];   // [64,16]
    const float* cf  = (const float*)d_in[1];   // [E,16]
    const float* w   = (const float*)d_in[2];   // [E]
    const int*   idx = (const int*)d_in[3];     // [E]
    int E = in_sizes[2];
    float* out = (float*)d_out;                 // [100000,64]

    int eb = (E + 255) / 256;
    int n4 = out_size / 4;

    k_count<<<eb, 256>>>(idx, w, E);
    k_scan1<<<NB, SCAN_BS>>>();
    k_scan23<<<NB, SCAN_BS>>>();
    k_scatter<<<eb, 256>>>(idx, w, (float4*)d_out, n4, E);

    int nt = (E + TILE - 1) / TILE;
    k_main<<<nt, K4_THREADS>>>(emb, cf, out, E);
}